// round 2
// baseline (speedup 1.0000x reference)
#include <cuda_runtime.h>
#include <math.h>

// Problem constants (fixed by the dataset)
#define BATCH   4
#define SEQ     4096
#define HID     2048
#define NHEADS  16
#define HDIM    128
#define FDIM    64
#define MROWS   (BATCH * SEQ)          // 16384
#define M2      (MROWS * NHEADS)       // 262144
#define BHEADS  (BATCH * NHEADS)       // 64
#define KVCH    16                     // split-K chunks for kv aggregation
#define KVELEM  (BHEADS * FDIM * HDIM) // 524288

// ---------------- scratch (static device globals; no allocation) -----------
__device__ float g_Q[(size_t)MROWS * HID];
__device__ float g_K[(size_t)MROWS * HID];
__device__ float g_V[(size_t)MROWS * HID];
__device__ float g_qp[(size_t)M2 * FDIM];
__device__ float g_kp[(size_t)M2 * FDIM];
__device__ float g_kvpart[(size_t)KVCH * KVELEM];
__device__ float g_kv[KVELEM];
__device__ float g_ksum[BHEADS * FDIM];
__device__ float g_attn[(size_t)MROWS * HID];

// ===========================================================================
// GEMM: C[M,N] = A[M,K] @ W[N,K]^T + bias[N]
// Both operands K-contiguous ("TN" form, matches torch Linear x@W.T).
// 128x128x16 block tile, 256 threads, 8x8 per thread, f32x2 packed FMA.
// A source: external ptr or g_attn (use_attn). C dest: csel 0/1/2 -> g_Q/K/V,
// csel 3 -> provided pointer (d_out).
// ===========================================================================
__global__ void __launch_bounds__(256, 2)
gemm_tn_bias(const float* __restrict__ Aext, int use_attn,
             const float* __restrict__ W, const float* __restrict__ bias,
             float* __restrict__ Cext, int csel,
             int M, int N, int K)
{
    const float* A = use_attn ? g_attn : Aext;
    float* C;
    switch (csel) {
        case 0: C = g_Q; break;
        case 1: C = g_K; break;
        case 2: C = g_V; break;
        default: C = Cext; break;
    }

    __shared__ float As[16][128];
    __shared__ float Bs[16][128];

    const int tid  = threadIdx.x;
    const int bm   = blockIdx.y * 128;
    const int bn   = blockIdx.x * 128;
    const int warp = tid >> 5, lane = tid & 31;
    // 8 warps: 4 (M) x 2 (N); lanes 4 (M) x 8 (N); 8x8 per thread
    const int row0 = (warp >> 1) * 32 + (lane >> 3) * 8;
    const int col0 = (warp & 1) * 64 + (lane & 7) * 8;

    unsigned long long acc[8][4];
    #pragma unroll
    for (int i = 0; i < 8; i++)
        #pragma unroll
        for (int j = 0; j < 4; j++) acc[i][j] = 0ULL;

    const float* Ab = A + (size_t)bm * K;
    const float* Wb = W + (size_t)bn * K;

    for (int k0 = 0; k0 < K; k0 += 16) {
        #pragma unroll
        for (int i = 0; i < 2; i++) {
            int idx = tid + 256 * i;          // 0..511
            int r   = idx >> 2;               // 0..127
            int c4  = (idx & 3) * 4;          // 0,4,8,12
            float4 av = *(const float4*)(Ab + (size_t)r * K + k0 + c4);
            As[c4 + 0][r] = av.x; As[c4 + 1][r] = av.y;
            As[c4 + 2][r] = av.z; As[c4 + 3][r] = av.w;
            float4 wv = *(const float4*)(Wb + (size_t)r * K + k0 + c4);
            Bs[c4 + 0][r] = wv.x; Bs[c4 + 1][r] = wv.y;
            Bs[c4 + 2][r] = wv.z; Bs[c4 + 3][r] = wv.w;
        }
        __syncthreads();

        #pragma unroll
        for (int k = 0; k < 16; k++) {
            float a[8];
            *(float4*)&a[0] = *(const float4*)&As[k][row0];
            *(float4*)&a[4] = *(const float4*)&As[k][row0 + 4];
            unsigned long long bv[4];
            {
                const unsigned long long* bp =
                    (const unsigned long long*)&Bs[k][col0];
                bv[0] = bp[0]; bv[1] = bp[1]; bv[2] = bp[2]; bv[3] = bp[3];
            }
            #pragma unroll
            for (int i = 0; i < 8; i++) {
                unsigned long long av2;
                asm("mov.b64 %0, {%1, %1};" : "=l"(av2) : "f"(a[i]));
                #pragma unroll
                for (int j = 0; j < 4; j++)
                    asm("fma.rn.f32x2 %0, %1, %2, %0;"
                        : "+l"(acc[i][j]) : "l"(av2), "l"(bv[j]));
            }
        }
        __syncthreads();
    }

    #pragma unroll
    for (int i = 0; i < 8; i++) {
        size_t rbase = (size_t)(bm + row0 + i) * N + bn + col0;
        #pragma unroll
        for (int j = 0; j < 4; j++) {
            float2 v = *reinterpret_cast<const float2*>(&acc[i][j]);
            int c = bn + col0 + 2 * j;
            v.x += bias[c];
            v.y += bias[c + 1];
            *(float2*)(C + rbase + 2 * j) = v;
        }
    }
}

// ===========================================================================
// Feature map: out[r,f] = relu( X[r, 0:128] . Wf[f, 0:128] ) (* mask[r/NH])
// X viewed as [M2, HDIM] (head split is contiguous). 16 rows/block.
// ===========================================================================
__global__ void __launch_bounds__(256)
feature_kernel(int is_k, const float* __restrict__ Wf,
               const float* __restrict__ mask)
{
    const float* X   = is_k ? g_K : g_Q;
    float*       out = is_k ? g_kp : g_qp;

    __shared__ float Ws[FDIM][HDIM + 1];   // +1 pad: conflict-free reads
    __shared__ float Xs[16][HDIM];

    const int tid = threadIdx.x;
    const int r0  = blockIdx.x * 16;

    #pragma unroll
    for (int i = 0; i < 8; i++) {
        int idx = tid + 256 * i;           // 0..2047 float4s
        int fr  = idx >> 5;
        int c4  = (idx & 31) * 4;
        float4 w = *(const float4*)(Wf + (size_t)fr * HDIM + c4);
        Ws[fr][c4 + 0] = w.x; Ws[fr][c4 + 1] = w.y;
        Ws[fr][c4 + 2] = w.z; Ws[fr][c4 + 3] = w.w;
    }
    #pragma unroll
    for (int i = 0; i < 2; i++) {
        int idx = tid + 256 * i;           // 0..511 float4s
        int rr  = idx >> 5;
        int c4  = (idx & 31) * 4;
        *(float4*)&Xs[rr][c4] =
            *(const float4*)(X + (size_t)(r0 + rr) * HDIM + c4);
    }
    __syncthreads();

    const int f  = tid & 63;
    const int rg = tid >> 6;               // 0..3 -> rows rg*4..rg*4+3
    float s[4] = {0.f, 0.f, 0.f, 0.f};
    #pragma unroll 8
    for (int d = 0; d < HDIM; d++) {
        float w = Ws[f][d];
        #pragma unroll
        for (int i = 0; i < 4; i++) s[i] += Xs[rg * 4 + i][d] * w;
    }
    #pragma unroll
    for (int i = 0; i < 4; i++) {
        int row = r0 + rg * 4 + i;
        float v = fmaxf(s[i], 0.0f);
        if (is_k) v *= mask[row >> 4];     // row / NHEADS (==16)
        out[(size_t)row * FDIM + f] = v;
    }
}

// ===========================================================================
// kv partial: for (chunk, bh): kvpart[chunk,bh,f,e] = sum_{s in chunk}
//   kp[b,s,h,f] * V[b,s,h*128+e].   Deterministic (no atomics).
// ===========================================================================
__global__ void __launch_bounds__(256)
kv_partial_kernel()
{
    __shared__ float ks[32][FDIM];
    __shared__ float vs[32][HDIM];

    const int tid = threadIdx.x;
    const int bh  = blockIdx.y;
    const int b   = bh >> 4, h = bh & 15;
    const int s0  = blockIdx.x * (SEQ / KVCH);   // 256 s per chunk
    const int fg  = tid >> 4;                    // f = fg*4
    const int eg  = tid & 15;                    // e = eg*8

    float acc[4][8];
    #pragma unroll
    for (int i = 0; i < 4; i++)
        #pragma unroll
        for (int j = 0; j < 8; j++) acc[i][j] = 0.f;

    for (int ss = 0; ss < SEQ / KVCH; ss += 32) {
        #pragma unroll
        for (int i = 0; i < 2; i++) {
            int idx = tid + 256 * i;             // 0..511 float4s (32x64)
            int sr  = idx >> 4;
            int c4  = (idx & 15) * 4;
            *(float4*)&ks[sr][c4] = *(const float4*)(
                g_kp + ((size_t)(b * SEQ + s0 + ss + sr) * NHEADS + h) * FDIM + c4);
        }
        #pragma unroll
        for (int i = 0; i < 4; i++) {
            int idx = tid + 256 * i;             // 0..1023 float4s (32x128)
            int sr  = idx >> 5;
            int c4  = (idx & 31) * 4;
            *(float4*)&vs[sr][c4] = *(const float4*)(
                g_V + (size_t)(b * SEQ + s0 + ss + sr) * HID + h * HDIM + c4);
        }
        __syncthreads();

        #pragma unroll 4
        for (int s = 0; s < 32; s++) {
            float a[4];
            *(float4*)a = *(const float4*)&ks[s][fg * 4];
            float bb[8];
            *(float4*)&bb[0] = *(const float4*)&vs[s][eg * 8];
            *(float4*)&bb[4] = *(const float4*)&vs[s][eg * 8 + 4];
            #pragma unroll
            for (int i = 0; i < 4; i++)
                #pragma unroll
                for (int j = 0; j < 8; j++) acc[i][j] += a[i] * bb[j];
        }
        __syncthreads();
    }

    float* dst = g_kvpart + ((size_t)blockIdx.x * BHEADS + bh) * FDIM * HDIM;
    #pragma unroll
    for (int i = 0; i < 4; i++) {
        #pragma unroll
        for (int j = 0; j < 8; j++)
            dst[(fg * 4 + i) * HDIM + eg * 8 + j] = acc[i][j];
    }
}

__global__ void __launch_bounds__(256)
kv_reduce_kernel()
{
    int i = blockIdx.x * 256 + threadIdx.x;      // 0..KVELEM-1
    float s = 0.f;
    #pragma unroll
    for (int c = 0; c < KVCH; c++) s += g_kvpart[(size_t)c * KVELEM + i];
    g_kv[i] = s;
}

// ===========================================================================
// k_sum[bh,f] = sum_s kp[b,s,h,f]   (mask already applied in kp)
// ===========================================================================
__global__ void __launch_bounds__(256)
ksum_kernel()
{
    const int bh = blockIdx.x;
    const int b  = bh >> 4, h = bh & 15;
    const int f    = threadIdx.x & 63;
    const int part = threadIdx.x >> 6;           // 0..3
    float s = 0.f;
    for (int si = part; si < SEQ; si += 4)
        s += g_kp[((size_t)(b * SEQ + si) * NHEADS + h) * FDIM + f];
    __shared__ float red[4][FDIM];
    red[part][f] = s;
    __syncthreads();
    if (part == 0)
        g_ksum[bh * FDIM + f] = red[0][f] + red[1][f] + red[2][f] + red[3][f];
}

// ===========================================================================
// qkv + normalize: attn[bs, h*128+e] =
//   (sum_f qp[bs,h,f]*kv[bh,f,e]) / (sum_f qp[bs,h,f]*ksum[bh,f] + 1e-8)
// One block = (32 bs rows) x (one head).
// ===========================================================================
__global__ void __launch_bounds__(256)
qkv_kernel()
{
    __shared__ float kvs[FDIM][HDIM];            // 32 KB
    __shared__ float qs[32][FDIM];               // 8 KB
    __shared__ float kss[FDIM];

    const int tid = threadIdx.x;
    const int h   = blockIdx.y;
    const int bs0 = blockIdx.x * 32;             // never crosses batch (SEQ%32==0)
    const int b   = bs0 / SEQ;
    const int bh  = b * NHEADS + h;

    #pragma unroll
    for (int i = 0; i < 8; i++) {
        int idx = tid + 256 * i;                 // 0..2047 float4s (64x128)
        int fr  = idx >> 5;
        int c4  = (idx & 31) * 4;
        *(float4*)&kvs[fr][c4] = *(const float4*)(
            g_kv + (size_t)bh * FDIM * HDIM + fr * HDIM + c4);
    }
    if (tid < FDIM) kss[tid] = g_ksum[bh * FDIM + tid];
    #pragma unroll
    for (int i = 0; i < 2; i++) {
        int idx = tid + 256 * i;                 // 0..511 float4s (32x64)
        int sr  = idx >> 4;
        int c4  = (idx & 15) * 4;
        *(float4*)&qs[sr][c4] = *(const float4*)(
            g_qp + ((size_t)(bs0 + sr) * NHEADS + h) * FDIM + c4);
    }
    __syncthreads();

    const int sl = tid >> 3;                     // 0..31 (row)
    const int e0 = (tid & 7) * 16;               // 16 outputs per thread

    float den = 0.f;
    #pragma unroll 8
    for (int f = 0; f < FDIM; f++) den += qs[sl][f] * kss[f];
    const float inv = 1.0f / (den + 1e-8f);

    float o[16];
    #pragma unroll
    for (int j = 0; j < 16; j++) o[j] = 0.f;
    #pragma unroll 4
    for (int f = 0; f < FDIM; f++) {
        float q = qs[sl][f];
        const float4* kr = (const float4*)&kvs[f][e0];
        #pragma unroll
        for (int j4 = 0; j4 < 4; j4++) {
            float4 kvv = kr[j4];
            o[j4 * 4 + 0] += q * kvv.x;
            o[j4 * 4 + 1] += q * kvv.y;
            o[j4 * 4 + 2] += q * kvv.z;
            o[j4 * 4 + 3] += q * kvv.w;
        }
    }

    float* dst = g_attn + (size_t)(bs0 + sl) * HID + h * HDIM + e0;
    #pragma unroll
    for (int j4 = 0; j4 < 4; j4++) {
        float4 v;
        v.x = o[j4 * 4 + 0] * inv;
        v.y = o[j4 * 4 + 1] * inv;
        v.z = o[j4 * 4 + 2] * inv;
        v.w = o[j4 * 4 + 3] * inv;
        *(float4*)(dst + j4 * 4) = v;
    }
}

// ===========================================================================
extern "C" void kernel_launch(void* const* d_in, const int* in_sizes, int n_in,
                              void* d_out, int out_size)
{
    const float* query = (const float*)d_in[0];
    const float* key_  = (const float*)d_in[1];
    const float* value = (const float*)d_in[2];
    const float* mask  = (const float*)d_in[3];
    const float* Wq    = (const float*)d_in[4];
    const float* bq    = (const float*)d_in[5];
    const float* Wk    = (const float*)d_in[6];
    const float* bk    = (const float*)d_in[7];
    const float* Wv    = (const float*)d_in[8];
    const float* bv    = (const float*)d_in[9];
    const float* Wqf   = (const float*)d_in[10];
    const float* Wkf   = (const float*)d_in[11];
    const float* Wo    = (const float*)d_in[12];
    const float* bo    = (const float*)d_in[13];
    float* out = (float*)d_out;

    dim3 gg(HID / 128, MROWS / 128);

    // Projections
    gemm_tn_bias<<<gg, 256>>>(query, 0, Wq, bq, nullptr, 0, MROWS, HID, HID);
    gemm_tn_bias<<<gg, 256>>>(key_,  0, Wk, bk, nullptr, 1, MROWS, HID, HID);
    gemm_tn_bias<<<gg, 256>>>(value, 0, Wv, bv, nullptr, 2, MROWS, HID, HID);

    // Feature maps (relu; mask folded into k')
    feature_kernel<<<M2 / 16, 256>>>(0, Wqf, nullptr);
    feature_kernel<<<M2 / 16, 256>>>(1, Wkf, mask);

    // Linear-attention aggregation
    kv_partial_kernel<<<dim3(KVCH, BHEADS), 256>>>();
    kv_reduce_kernel<<<KVELEM / 256, 256>>>();
    ksum_kernel<<<BHEADS, 256>>>();
    qkv_kernel<<<dim3(MROWS / 32, NHEADS), 256>>>();

    // Output projection -> d_out
    gemm_tn_bias<<<gg, 256>>>(nullptr, 1, Wo, bo, out, 3, MROWS, HID, HID);
}

// round 4
// speedup vs baseline: 2.9359x; 2.9359x over previous
#include <cuda_runtime.h>
#include <cuda_bf16.h>
#include <cstdint>

// Problem constants (fixed by the dataset)
#define BATCH   4
#define SEQ     4096
#define HID     2048
#define NHEADS  16
#define HDIM    128
#define FDIM    64
#define MROWS   (BATCH * SEQ)          // 16384
#define M2      (MROWS * NHEADS)       // 262144
#define BHEADS  (BATCH * NHEADS)       // 64
#define KVCH    16
#define KVELEM  (BHEADS * FDIM * HDIM) // 524288
#define NQP     (NHEADS * FDIM)        // 1024 (combined q'/k' projection width)

// ---------------- scratch (static device globals; no allocation) -----------
__device__ float g_V[(size_t)MROWS * HID];
__device__ float g_qp[(size_t)M2 * FDIM];
__device__ float g_kp[(size_t)M2 * FDIM];
__device__ float g_kvpart[(size_t)KVCH * KVELEM];
__device__ float g_kv[KVELEM];
__device__ float g_ksum[BHEADS * FDIM];
__device__ float g_attn[(size_t)MROWS * HID];
__device__ float g_Wqc[(size_t)NQP * HID];
__device__ float g_Wkc[(size_t)NQP * HID];
__device__ float g_bqc[NQP];
__device__ float g_bkc[NQP];

// =========================== helpers =======================================
__device__ __forceinline__ uint32_t smem_u32(const void* p) {
    uint32_t a;
    asm("{ .reg .u64 t; cvta.to.shared.u64 t, %1; cvt.u32.u64 %0, t; }"
        : "=r"(a) : "l"(p));
    return a;
}
#define SMEM_SWIZZLE_128B(off) ((off) ^ (((off) >> 3) & 0x70))

__device__ __forceinline__ void ldsm_x4(uint32_t& r0, uint32_t& r1,
                                        uint32_t& r2, uint32_t& r3,
                                        uint32_t addr) {
    asm volatile("ldmatrix.sync.aligned.m8n8.x4.shared.b16 {%0,%1,%2,%3}, [%4];"
                 : "=r"(r0), "=r"(r1), "=r"(r2), "=r"(r3) : "r"(addr));
}
__device__ __forceinline__ void mma_bf16(float* d, const uint32_t* a,
                                         const uint32_t* b) {
    asm volatile(
        "mma.sync.aligned.m16n8k16.row.col.f32.bf16.bf16.f32 "
        "{%0,%1,%2,%3}, {%4,%5,%6,%7}, {%8,%9}, {%0,%1,%2,%3};"
        : "+f"(d[0]), "+f"(d[1]), "+f"(d[2]), "+f"(d[3])
        : "r"(a[0]), "r"(a[1]), "r"(a[2]), "r"(a[3]), "r"(b[0]), "r"(b[1]));
}

__device__ __forceinline__ void split_pack(float x, float y, uint32_t& h, uint32_t& l) {
    __nv_bfloat16 hx = __float2bfloat16(x);
    __nv_bfloat16 hy = __float2bfloat16(y);
    h = (uint32_t)__bfloat16_as_ushort(hx) |
        ((uint32_t)__bfloat16_as_ushort(hy) << 16);
    __nv_bfloat16 lx = __float2bfloat16(x - __bfloat162float(hx));
    __nv_bfloat16 ly = __float2bfloat16(y - __bfloat162float(hy));
    l = (uint32_t)__bfloat16_as_ushort(lx) |
        ((uint32_t)__bfloat16_as_ushort(ly) << 16);
}

// ===========================================================================
// Tensor-core GEMM via mma.sync bf16 3-term split:
//   C[M,N] = A[M,K=2048] @ W[N,K]^T + bias   [, relu][, row-mask]
// 128x128 tile, K-chunk 64 (128B bf16 rows, SW128 swizzle), 256 thr, 2 CTA/SM.
// ===========================================================================
#define TILE_K   64
#define CHUNKS   (HID / TILE_K)   // 32
#define TSB      16384            // one 128x64-bf16 tile in bytes
#define OFF_AH   0
#define OFF_AL   TSB
#define OFF_BH   (2 * TSB)
#define OFF_BL   (3 * TSB)
#define GSMEM    (4 * TSB)        // 65536

__global__ void __launch_bounds__(256, 2)
gemm_tc(const float* __restrict__ Aext, int asel,
        const float* __restrict__ Wext, int wsel,
        const float* __restrict__ bext, int bsel,
        float* __restrict__ Cext, int csel,
        const float* __restrict__ mask, int flags,   // bit0 relu, bit1 mask
        int N)
{
    extern __shared__ char smem[];
    const float* A    = asel ? g_attn : Aext;
    const float* W    = (wsel == 1) ? g_Wqc : (wsel == 2) ? g_Wkc : Wext;
    const float* bias = (bsel == 1) ? g_bqc : (bsel == 2) ? g_bkc : bext;
    float* C = (csel == 0) ? g_qp : (csel == 1) ? g_kp : (csel == 2) ? g_V : Cext;

    const uint32_t sb = smem_u32(smem);
    const int tid  = threadIdx.x;
    const int lane = tid & 31;
    const int wid  = tid >> 5;
    const int wm   = wid >> 2;         // 0..1  (M: 2 x 64)
    const int wn   = wid & 3;          // 0..3  (N: 4 x 32)
    const int bn   = blockIdx.x * 128;
    const int bm   = blockIdx.y * 128;

    const float* Ab = A + (size_t)bm * HID;
    const float* Wb = W + (size_t)bn * HID;

    // ldmatrix per-lane base offsets (bytes within a tile)
    // A: row = wm*64 + mf*16 + (lane&15); k byte offset += (lane>>4)*16
    const uint32_t a_row  = (uint32_t)(wm * 64 + (lane & 15));
    const uint32_t a_kofs = (uint32_t)((lane >> 4) * 16);
    // B: row(n) = wn*32 + nf2*16 + (lane&7) + ((lane&16)>>1); k ofs += (lane&8)*2
    const uint32_t b_row  = (uint32_t)(wn * 32 + (lane & 7) + ((lane & 16) >> 1));
    const uint32_t b_kofs = (uint32_t)((lane & 8) * 2);

    float acc[4][4][4];
    #pragma unroll
    for (int mf = 0; mf < 4; mf++)
        #pragma unroll
        for (int nf = 0; nf < 4; nf++)
            #pragma unroll
            for (int j = 0; j < 4; j++) acc[mf][nf][j] = 0.f;

    #pragma unroll 1
    for (int c = 0; c < CHUNKS; c++) {
        const int k0 = c * TILE_K;
        __syncthreads();                       // prior mma reads done
        // ---- stage A (hi/lo) ----
        #pragma unroll
        for (int i = 0; i < 8; i++) {
            int idx = tid + 256 * i;           // 0..2047 float4s
            int r   = idx >> 4;                // 0..127
            int c4  = (idx & 15) * 4;          // 0..60
            float4 v = *(const float4*)(Ab + (size_t)r * HID + k0 + c4);
            uint32_t h01, h23, l01, l23;
            split_pack(v.x, v.y, h01, l01);
            split_pack(v.z, v.w, h23, l23);
            uint32_t off = SMEM_SWIZZLE_128B((uint32_t)(r * 128 + c4 * 2));
            *(uint2*)(smem + OFF_AH + off) = make_uint2(h01, h23);
            *(uint2*)(smem + OFF_AL + off) = make_uint2(l01, l23);
        }
        // ---- stage B (hi/lo) ----
        #pragma unroll
        for (int i = 0; i < 8; i++) {
            int idx = tid + 256 * i;
            int r   = idx >> 4;
            int c4  = (idx & 15) * 4;
            float4 v = *(const float4*)(Wb + (size_t)r * HID + k0 + c4);
            uint32_t h01, h23, l01, l23;
            split_pack(v.x, v.y, h01, l01);
            split_pack(v.z, v.w, h23, l23);
            uint32_t off = SMEM_SWIZZLE_128B((uint32_t)(r * 128 + c4 * 2));
            *(uint2*)(smem + OFF_BH + off) = make_uint2(h01, h23);
            *(uint2*)(smem + OFF_BL + off) = make_uint2(l01, l23);
        }
        __syncthreads();

        // ---- 4 k-steps of mma ----
        #pragma unroll
        for (int ks = 0; ks < 4; ks++) {
            const uint32_t kb = (uint32_t)(ks * 32);   // k0 within chunk, bytes
            uint32_t bh[8], bl[8];
            #pragma unroll
            for (int nf2 = 0; nf2 < 2; nf2++) {
                uint32_t off = SMEM_SWIZZLE_128B(
                    (b_row + nf2 * 16) * 128 + kb + b_kofs);
                ldsm_x4(bh[nf2*4+0], bh[nf2*4+1], bh[nf2*4+2], bh[nf2*4+3],
                        sb + OFF_BH + off);
                ldsm_x4(bl[nf2*4+0], bl[nf2*4+1], bl[nf2*4+2], bl[nf2*4+3],
                        sb + OFF_BL + off);
            }
            #pragma unroll
            for (int mf = 0; mf < 4; mf++) {
                uint32_t aoff = SMEM_SWIZZLE_128B(
                    (a_row + mf * 16) * 128 + kb + a_kofs);
                uint32_t ah[4], al[4];
                ldsm_x4(ah[0], ah[1], ah[2], ah[3], sb + OFF_AH + aoff);
                ldsm_x4(al[0], al[1], al[2], al[3], sb + OFF_AL + aoff);
                #pragma unroll
                for (int nf = 0; nf < 4; nf++) {
                    mma_bf16(acc[mf][nf], ah, &bh[nf * 2]);   // hi*hi
                    mma_bf16(acc[mf][nf], ah, &bl[nf * 2]);   // hi*lo
                    mma_bf16(acc[mf][nf], al, &bh[nf * 2]);   // lo*hi
                }
            }
        }
    }

    // ---- epilogue: bias [+relu][+mask], direct global stores ----
    const int tq = lane >> 2;       // 0..7
    const int tr = lane & 3;        // 0..3
    float2 bv[4];
    #pragma unroll
    for (int nf = 0; nf < 4; nf++) {
        int col = bn + wn * 32 + nf * 8 + tr * 2;
        bv[nf].x = bias[col];
        bv[nf].y = bias[col + 1];
    }
    #pragma unroll
    for (int mf = 0; mf < 4; mf++) {
        #pragma unroll
        for (int half = 0; half < 2; half++) {
            int row = bm + wm * 64 + mf * 16 + tq + half * 8;
            float mv = (flags & 2) ? mask[row] : 1.0f;
            float* dst = C + (size_t)row * N + bn + wn * 32 + tr * 2;
            #pragma unroll
            for (int nf = 0; nf < 4; nf++) {
                float2 v;
                v.x = acc[mf][nf][half * 2 + 0] + bv[nf].x;
                v.y = acc[mf][nf][half * 2 + 1] + bv[nf].y;
                if (flags & 1) { v.x = fmaxf(v.x, 0.f); v.y = fmaxf(v.y, 0.f); }
                v.x *= mv; v.y *= mv;
                *(float2*)(dst + nf * 8) = v;
            }
        }
    }
}

// ===========================================================================
// Combined-weight precompute: Wc[h*64+f, e] = sum_d Wf[f,d] * Wbig[h*128+d, e]
// ===========================================================================
__global__ void __launch_bounds__(256)
comb_kernel(const float* __restrict__ Wq, const float* __restrict__ Wqf,
            const float* __restrict__ Wk, const float* __restrict__ Wkf)
{
    const int isk = blockIdx.z;
    const float* Wbig = isk ? Wk : Wq;
    const float* Wf   = isk ? Wkf : Wqf;
    float* out = isk ? g_Wkc : g_Wqc;
    const int h  = blockIdx.y;
    const int e0 = blockIdx.x * 128;

    __shared__ float Wfs[FDIM][HDIM + 1];
    __shared__ float Ws[16][128];

    const int tid = threadIdx.x;
    for (int idx = tid; idx < FDIM * HDIM; idx += 256)
        Wfs[idx >> 7][idx & 127] = Wf[idx];

    const int f  = tid & 63;
    const int eg = tid >> 6;
    float acc[32];
    #pragma unroll
    for (int j = 0; j < 32; j++) acc[j] = 0.f;

    for (int d0 = 0; d0 < HDIM; d0 += 16) {
        __syncthreads();
        #pragma unroll
        for (int i = 0; i < 2; i++) {
            int idx = tid + 256 * i;
            int dd  = idx >> 5;
            int c4  = (idx & 31) * 4;
            *(float4*)&Ws[dd][c4] =
                *(const float4*)(Wbig + (size_t)(h * HDIM + d0 + dd) * HID + e0 + c4);
        }
        __syncthreads();
        #pragma unroll
        for (int dd = 0; dd < 16; dd++) {
            float wf = Wfs[f][d0 + dd];
            #pragma unroll
            for (int j = 0; j < 32; j++)
                acc[j] += wf * Ws[dd][eg * 32 + j];
        }
    }
    #pragma unroll
    for (int j = 0; j < 32; j++)
        out[(size_t)(h * FDIM + f) * HID + e0 + eg * 32 + j] = acc[j];
}

__global__ void __launch_bounds__(64)
bias_comb_kernel(const float* __restrict__ bq, const float* __restrict__ Wqf,
                 const float* __restrict__ bk, const float* __restrict__ Wkf)
{
    const int isk = blockIdx.y;
    const float* b  = isk ? bk : bq;
    const float* Wf = isk ? Wkf : Wqf;
    float* out = isk ? g_bkc : g_bqc;
    const int h = blockIdx.x;
    const int f = threadIdx.x;
    float s = 0.f;
    for (int d = 0; d < HDIM; d++) s += Wf[f * HDIM + d] * b[h * HDIM + d];
    out[h * FDIM + f] = s;
}

// ===========================================================================
// kv partial (deterministic split-K), reduce, ksum, qkv
// ===========================================================================
__global__ void __launch_bounds__(256)
kv_partial_kernel()
{
    __shared__ float ks[32][FDIM];
    __shared__ float vs[32][HDIM];

    const int tid = threadIdx.x;
    const int bh  = blockIdx.y;
    const int b   = bh >> 4, h = bh & 15;
    const int s0  = blockIdx.x * (SEQ / KVCH);
    const int fg  = tid >> 4;
    const int eg  = tid & 15;

    float acc[4][8];
    #pragma unroll
    for (int i = 0; i < 4; i++)
        #pragma unroll
        for (int j = 0; j < 8; j++) acc[i][j] = 0.f;

    for (int ss = 0; ss < SEQ / KVCH; ss += 32) {
        #pragma unroll
        for (int i = 0; i < 2; i++) {
            int idx = tid + 256 * i;
            int sr  = idx >> 4;
            int c4  = (idx & 15) * 4;
            *(float4*)&ks[sr][c4] = *(const float4*)(
                g_kp + ((size_t)(b * SEQ + s0 + ss + sr) * NHEADS + h) * FDIM + c4);
        }
        #pragma unroll
        for (int i = 0; i < 4; i++) {
            int idx = tid + 256 * i;
            int sr  = idx >> 5;
            int c4  = (idx & 31) * 4;
            *(float4*)&vs[sr][c4] = *(const float4*)(
                g_V + (size_t)(b * SEQ + s0 + ss + sr) * HID + h * HDIM + c4);
        }
        __syncthreads();

        #pragma unroll 4
        for (int s = 0; s < 32; s++) {
            float a[4];
            *(float4*)a = *(const float4*)&ks[s][fg * 4];
            float bb[8];
            *(float4*)&bb[0] = *(const float4*)&vs[s][eg * 8];
            *(float4*)&bb[4] = *(const float4*)&vs[s][eg * 8 + 4];
            #pragma unroll
            for (int i = 0; i < 4; i++)
                #pragma unroll
                for (int j = 0; j < 8; j++) acc[i][j] += a[i] * bb[j];
        }
        __syncthreads();
    }

    float* dst = g_kvpart + ((size_t)blockIdx.x * BHEADS + bh) * FDIM * HDIM;
    #pragma unroll
    for (int i = 0; i < 4; i++)
        #pragma unroll
        for (int j = 0; j < 8; j++)
            dst[(fg * 4 + i) * HDIM + eg * 8 + j] = acc[i][j];
}

__global__ void __launch_bounds__(256)
kv_reduce_kernel()
{
    int i = blockIdx.x * 256 + threadIdx.x;
    float s = 0.f;
    #pragma unroll
    for (int c = 0; c < KVCH; c++) s += g_kvpart[(size_t)c * KVELEM + i];
    g_kv[i] = s;
}

__global__ void __launch_bounds__(256)
ksum_kernel()
{
    const int bh = blockIdx.x;
    const int b  = bh >> 4, h = bh & 15;
    const int f    = threadIdx.x & 63;
    const int part = threadIdx.x >> 6;
    float s = 0.f;
    for (int si = part; si < SEQ; si += 4)
        s += g_kp[((size_t)(b * SEQ + si) * NHEADS + h) * FDIM + f];
    __shared__ float red[4][FDIM];
    red[part][f] = s;
    __syncthreads();
    if (part == 0)
        g_ksum[bh * FDIM + f] = red[0][f] + red[1][f] + red[2][f] + red[3][f];
}

__global__ void __launch_bounds__(256)
qkv_kernel()
{
    __shared__ float kvs[FDIM][HDIM];
    __shared__ float qs[32][FDIM];
    __shared__ float kss[FDIM];

    const int tid = threadIdx.x;
    const int h   = blockIdx.y;
    const int bs0 = blockIdx.x * 32;
    const int b   = bs0 / SEQ;
    const int bh  = b * NHEADS + h;

    #pragma unroll
    for (int i = 0; i < 8; i++) {
        int idx = tid + 256 * i;
        int fr  = idx >> 5;
        int c4  = (idx & 31) * 4;
        *(float4*)&kvs[fr][c4] = *(const float4*)(
            g_kv + (size_t)bh * FDIM * HDIM + fr * HDIM + c4);
    }
    if (tid < FDIM) kss[tid] = g_ksum[bh * FDIM + tid];
    #pragma unroll
    for (int i = 0; i < 2; i++) {
        int idx = tid + 256 * i;
        int sr  = idx >> 4;
        int c4  = (idx & 15) * 4;
        *(float4*)&qs[sr][c4] = *(const float4*)(
            g_qp + ((size_t)(bs0 + sr) * NHEADS + h) * FDIM + c4);
    }
    __syncthreads();

    const int sl = tid >> 3;
    const int e0 = (tid & 7) * 16;

    float den = 0.f;
    #pragma unroll 8
    for (int f = 0; f < FDIM; f++) den += qs[sl][f] * kss[f];
    const float inv = 1.0f / (den + 1e-8f);

    float o[16];
    #pragma unroll
    for (int j = 0; j < 16; j++) o[j] = 0.f;
    #pragma unroll 4
    for (int f = 0; f < FDIM; f++) {
        float q = qs[sl][f];
        const float4* kr = (const float4*)&kvs[f][e0];
        #pragma unroll
        for (int j4 = 0; j4 < 4; j4++) {
            float4 kvv = kr[j4];
            o[j4 * 4 + 0] += q * kvv.x;
            o[j4 * 4 + 1] += q * kvv.y;
            o[j4 * 4 + 2] += q * kvv.z;
            o[j4 * 4 + 3] += q * kvv.w;
        }
    }

    float* dst = g_attn + (size_t)(bs0 + sl) * HID + h * HDIM + e0;
    #pragma unroll
    for (int j4 = 0; j4 < 4; j4++) {
        float4 v;
        v.x = o[j4 * 4 + 0] * inv;
        v.y = o[j4 * 4 + 1] * inv;
        v.z = o[j4 * 4 + 2] * inv;
        v.w = o[j4 * 4 + 3] * inv;
        *(float4*)(dst + j4 * 4) = v;
    }
}

// ===========================================================================
extern "C" void kernel_launch(void* const* d_in, const int* in_sizes, int n_in,
                              void* d_out, int out_size)
{
    const float* query = (const float*)d_in[0];
    const float* key_  = (const float*)d_in[1];
    const float* value = (const float*)d_in[2];
    const float* mask  = (const float*)d_in[3];
    const float* Wq    = (const float*)d_in[4];
    const float* bq    = (const float*)d_in[5];
    const float* Wk    = (const float*)d_in[6];
    const float* bk    = (const float*)d_in[7];
    const float* Wv    = (const float*)d_in[8];
    const float* bv    = (const float*)d_in[9];
    const float* Wqf   = (const float*)d_in[10];
    const float* Wkf   = (const float*)d_in[11];
    const float* Wo    = (const float*)d_in[12];
    const float* bo    = (const float*)d_in[13];
    float* out = (float*)d_out;

    cudaFuncSetAttribute(gemm_tc, cudaFuncAttributeMaxDynamicSharedMemorySize, GSMEM);

    // Combined q'/k' projection weights (fold Wq/Wk into Wqf/Wkf)
    comb_kernel<<<dim3(HID / 128, NHEADS, 2), 256>>>(Wq, Wqf, Wk, Wkf);
    bias_comb_kernel<<<dim3(NHEADS, 2), 64>>>(bq, Wqf, bk, Wkf);

    // q' = relu(query @ Wqc^T + bqc)      -> g_qp  [M, 16*64]
    gemm_tc<<<dim3(NQP / 128, MROWS / 128), 256, GSMEM>>>(
        query, 0, nullptr, 1, nullptr, 1, nullptr, 0, mask, 1, NQP);
    // k' = relu(key @ Wkc^T + bkc) * mask -> g_kp
    gemm_tc<<<dim3(NQP / 128, MROWS / 128), 256, GSMEM>>>(
        key_, 0, nullptr, 2, nullptr, 2, nullptr, 1, mask, 3, NQP);
    // V = value @ Wv^T + bv               -> g_V
    gemm_tc<<<dim3(HID / 128, MROWS / 128), 256, GSMEM>>>(
        value, 0, Wv, 0, bv, 0, nullptr, 2, mask, 0, HID);

    // Linear-attention aggregation
    kv_partial_kernel<<<dim3(KVCH, BHEADS), 256>>>();
    kv_reduce_kernel<<<KVELEM / 256, 256>>>();
    ksum_kernel<<<BHEADS, 256>>>();
    qkv_kernel<<<dim3(MROWS / 32, NHEADS), 256>>>();

    // out = attn @ Wo^T + bo
    gemm_tc<<<dim3(HID / 128, MROWS / 128), 256, GSMEM>>>(
        nullptr, 1, Wo, 0, bo, 0, out, 3, mask, 0, HID);
}

// round 6
// speedup vs baseline: 3.3921x; 1.1554x over previous
#include <cuda_runtime.h>
#include <cuda_bf16.h>
#include <cstdint>

// Problem constants (fixed by the dataset)
#define BATCH   4
#define SEQ     4096
#define HID     2048
#define NHEADS  16
#define HDIM    128
#define FDIM    64
#define MROWS   (BATCH * SEQ)          // 16384
#define M2      (MROWS * NHEADS)       // 262144
#define BHEADS  (BATCH * NHEADS)       // 64
#define KVCH    16
#define KVELEM  (BHEADS * FDIM * HDIM) // 524288
#define NQP     (NHEADS * FDIM)        // 1024

// ---------------- scratch (static device globals; no allocation) -----------
__device__ float g_V[(size_t)MROWS * HID];
__device__ float g_qp[(size_t)M2 * FDIM];
__device__ float g_kp[(size_t)M2 * FDIM];
__device__ float g_kvpart[(size_t)KVCH * KVELEM];
__device__ float g_kv[KVELEM];
__device__ float g_kspart[KVCH * BHEADS * FDIM];
__device__ float g_ksum[BHEADS * FDIM];
__device__ float g_bqc[NQP];
__device__ float g_bkc[NQP];
// bf16 hi/lo planes
__device__ __nv_bfloat16 g_qh[(size_t)MROWS * HID],  g_ql[(size_t)MROWS * HID];
__device__ __nv_bfloat16 g_kh[(size_t)MROWS * HID],  g_kl[(size_t)MROWS * HID];
__device__ __nv_bfloat16 g_vh[(size_t)MROWS * HID],  g_vl[(size_t)MROWS * HID];
__device__ __nv_bfloat16 g_ah[(size_t)MROWS * HID],  g_al[(size_t)MROWS * HID];
__device__ __nv_bfloat16 g_Wvh[(size_t)HID * HID],   g_Wvl[(size_t)HID * HID];
__device__ __nv_bfloat16 g_Woh[(size_t)HID * HID],   g_Wol[(size_t)HID * HID];
__device__ __nv_bfloat16 g_Wqch[(size_t)NQP * HID],  g_Wqcl[(size_t)NQP * HID];
__device__ __nv_bfloat16 g_Wkch[(size_t)NQP * HID],  g_Wkcl[(size_t)NQP * HID];

// =========================== helpers =======================================
__device__ __forceinline__ uint32_t smem_u32(const void* p) {
    uint32_t a;
    asm("{ .reg .u64 t; cvta.to.shared.u64 t, %1; cvt.u32.u64 %0, t; }"
        : "=r"(a) : "l"(p));
    return a;
}
#define SMEM_SWIZZLE_128B(off) ((off) ^ (((off) >> 3) & 0x70))

__device__ __forceinline__ void cp16(uint32_t dst, const void* src) {
    asm volatile("cp.async.cg.shared.global [%0], [%1], 16;"
                 :: "r"(dst), "l"(src) : "memory");
}
#define CP_COMMIT() asm volatile("cp.async.commit_group;" ::: "memory")
#define CP_WAIT1()  asm volatile("cp.async.wait_group 1;" ::: "memory")

__device__ __forceinline__ void ldsm_x4(uint32_t& r0, uint32_t& r1,
                                        uint32_t& r2, uint32_t& r3,
                                        uint32_t addr) {
    asm volatile("ldmatrix.sync.aligned.m8n8.x4.shared.b16 {%0,%1,%2,%3}, [%4];"
                 : "=r"(r0), "=r"(r1), "=r"(r2), "=r"(r3) : "r"(addr));
}
__device__ __forceinline__ void mma_bf16(float* d, const uint32_t* a,
                                         const uint32_t* b) {
    asm volatile(
        "mma.sync.aligned.m16n8k16.row.col.f32.bf16.bf16.f32 "
        "{%0,%1,%2,%3}, {%4,%5,%6,%7}, {%8,%9}, {%0,%1,%2,%3};"
        : "+f"(d[0]), "+f"(d[1]), "+f"(d[2]), "+f"(d[3])
        : "r"(a[0]), "r"(a[1]), "r"(a[2]), "r"(a[3]), "r"(b[0]), "r"(b[1]));
}
__device__ __forceinline__ void split_pack(float x, float y, uint32_t& h, uint32_t& l) {
    __nv_bfloat16 hx = __float2bfloat16(x);
    __nv_bfloat16 hy = __float2bfloat16(y);
    h = (uint32_t)__bfloat16_as_ushort(hx) |
        ((uint32_t)__bfloat16_as_ushort(hy) << 16);
    __nv_bfloat16 lx = __float2bfloat16(x - __bfloat162float(hx));
    __nv_bfloat16 ly = __float2bfloat16(y - __bfloat162float(hy));
    l = (uint32_t)__bfloat16_as_ushort(lx) |
        ((uint32_t)__bfloat16_as_ushort(ly) << 16);
}

// ===========================================================================
// fp32 -> bf16 hi/lo plane conversion (8 elements / thread)
// ===========================================================================
__global__ void __launch_bounds__(256)
conv_kernel(const float* __restrict__ src, int sel, int n8)
{
    __nv_bfloat16 *dh, *dl;
    switch (sel) {
        case 0: dh = g_qh;  dl = g_ql;  break;
        case 1: dh = g_kh;  dl = g_kl;  break;
        case 2: dh = g_vh;  dl = g_vl;  break;
        case 3: dh = g_Wvh; dl = g_Wvl; break;
        default: dh = g_Woh; dl = g_Wol; break;
    }
    int i = blockIdx.x * 256 + threadIdx.x;
    if (i >= n8) return;
    const float4* s4 = (const float4*)src + (size_t)i * 2;
    float4 v0 = s4[0], v1 = s4[1];
    uint32_t h[4], l[4];
    split_pack(v0.x, v0.y, h[0], l[0]);
    split_pack(v0.z, v0.w, h[1], l[1]);
    split_pack(v1.x, v1.y, h[2], l[2]);
    split_pack(v1.z, v1.w, h[3], l[3]);
    *(uint4*)(dh + (size_t)i * 8) = make_uint4(h[0], h[1], h[2], h[3]);
    *(uint4*)(dl + (size_t)i * 8) = make_uint4(l[0], l[1], l[2], l[3]);
}

// ===========================================================================
// Tensor-core GEMM, bf16 3-term split, cp.async 3-stage pipeline.
//   C[M,N] = A[M,2048] @ W[N,2048]^T + bias [,relu][,row-mask]
// 128x128 tile, K-chunk 64, 256 threads, 1 CTA/SM, 192KB smem.
// ===========================================================================
#define TILE_K   64
#define CHUNKS   (HID / TILE_K)   // 32
#define PLB      16384            // one 128x64-bf16 plane tile, bytes
#define STG      (4 * PLB)        // AH, AL, BH, BL
#define NSTAGE   3
#define GSMEM    (NSTAGE * STG)   // 196608

__device__ __forceinline__ void stage_load(
    uint32_t sbuf, const __nv_bfloat16* Abh, const __nv_bfloat16* Abl,
    const __nv_bfloat16* Bbh, const __nv_bfloat16* Bbl, int k0, int tid)
{
    #pragma unroll
    for (int i = 0; i < 4; i++) {
        int idx = tid + 256 * i;          // 0..1023
        int r   = idx >> 3;               // 0..127
        int s   = (idx & 7) * 8;          // element offset 0..56
        uint32_t off = SMEM_SWIZZLE_128B((uint32_t)(r * 128 + s * 2));
        size_t g = (size_t)r * HID + k0 + s;
        cp16(sbuf + 0 * PLB + off, Abh + g);
        cp16(sbuf + 1 * PLB + off, Abl + g);
        cp16(sbuf + 2 * PLB + off, Bbh + g);
        cp16(sbuf + 3 * PLB + off, Bbl + g);
    }
}

__global__ void __launch_bounds__(256, 1)
gemm_tc(int asel, int wsel, const float* __restrict__ bext, int bsel,
        float* __restrict__ Cext, int csel,
        const float* __restrict__ mask, int flags, int N)
{
    extern __shared__ char smem[];
    const __nv_bfloat16 *Ah, *Al, *Wh, *Wl;
    switch (asel) {
        case 0: Ah = g_qh; Al = g_ql; break;
        case 1: Ah = g_kh; Al = g_kl; break;
        case 2: Ah = g_vh; Al = g_vl; break;
        default: Ah = g_ah; Al = g_al; break;
    }
    switch (wsel) {
        case 0: Wh = g_Wqch; Wl = g_Wqcl; break;
        case 1: Wh = g_Wkch; Wl = g_Wkcl; break;
        case 2: Wh = g_Wvh;  Wl = g_Wvl;  break;
        default: Wh = g_Woh; Wl = g_Wol; break;
    }
    const float* bias = (bsel == 0) ? g_bqc : (bsel == 1) ? g_bkc : bext;
    float* C = (csel == 0) ? g_qp : (csel == 1) ? g_kp : (csel == 2) ? g_V : Cext;

    const uint32_t sb = smem_u32(smem);
    const int tid  = threadIdx.x;
    const int lane = tid & 31;
    const int wid  = tid >> 5;
    const int wm   = wid >> 2;         // 0..1  (M: 2 x 64)
    const int wn   = wid & 3;          // 0..3  (N: 4 x 32)
    const int bn   = blockIdx.x * 128;
    const int bm   = blockIdx.y * 128;

    const __nv_bfloat16* Abh = Ah + (size_t)bm * HID;
    const __nv_bfloat16* Abl = Al + (size_t)bm * HID;
    const __nv_bfloat16* Bbh = Wh + (size_t)bn * HID;
    const __nv_bfloat16* Bbl = Wl + (size_t)bn * HID;

    const uint32_t a_row  = (uint32_t)(wm * 64 + (lane & 15));
    const uint32_t a_kofs = (uint32_t)((lane >> 4) * 16);
    const uint32_t b_row  = (uint32_t)(wn * 32 + (lane & 7) + ((lane & 16) >> 1));
    const uint32_t b_kofs = (uint32_t)((lane & 8) * 2);

    float acc[4][4][4];
    #pragma unroll
    for (int mf = 0; mf < 4; mf++)
        #pragma unroll
        for (int nf = 0; nf < 4; nf++)
            #pragma unroll
            for (int j = 0; j < 4; j++) acc[mf][nf][j] = 0.f;

    // prologue: prefetch stages 0,1
    stage_load(sb + 0 * STG, Abh, Abl, Bbh, Bbl, 0, tid);
    CP_COMMIT();
    stage_load(sb + 1 * STG, Abh, Abl, Bbh, Bbl, TILE_K, tid);
    CP_COMMIT();

    #pragma unroll 1
    for (int c = 0; c < CHUNKS; c++) {
        CP_WAIT1();
        __syncthreads();

        const int pf = c + 2;
        if (pf < CHUNKS)
            stage_load(sb + (pf % NSTAGE) * STG, Abh, Abl, Bbh, Bbl,
                       pf * TILE_K, tid);
        CP_COMMIT();   // empty commit groups are legal no-ops

        const uint32_t sbase = sb + (c % NSTAGE) * STG;
        #pragma unroll
        for (int ks = 0; ks < 4; ks++) {
            const uint32_t kb = (uint32_t)(ks * 32);
            uint32_t bh[8], bl[8];
            #pragma unroll
            for (int nf2 = 0; nf2 < 2; nf2++) {
                uint32_t off = SMEM_SWIZZLE_128B(
                    (b_row + nf2 * 16) * 128 + kb + b_kofs);
                ldsm_x4(bh[nf2*4+0], bh[nf2*4+1], bh[nf2*4+2], bh[nf2*4+3],
                        sbase + 2 * PLB + off);
                ldsm_x4(bl[nf2*4+0], bl[nf2*4+1], bl[nf2*4+2], bl[nf2*4+3],
                        sbase + 3 * PLB + off);
            }
            #pragma unroll
            for (int mf = 0; mf < 4; mf++) {
                uint32_t aoff = SMEM_SWIZZLE_128B(
                    (a_row + mf * 16) * 128 + kb + a_kofs);
                uint32_t ah[4], al[4];
                ldsm_x4(ah[0], ah[1], ah[2], ah[3], sbase + 0 * PLB + aoff);
                ldsm_x4(al[0], al[1], al[2], al[3], sbase + 1 * PLB + aoff);
                #pragma unroll
                for (int nf = 0; nf < 4; nf++) {
                    mma_bf16(acc[mf][nf], ah, &bh[nf * 2]);   // hi*hi
                    mma_bf16(acc[mf][nf], ah, &bl[nf * 2]);   // hi*lo
                    mma_bf16(acc[mf][nf], al, &bh[nf * 2]);   // lo*hi
                }
            }
        }
    }

    // ---- epilogue ----
    const int tq = lane >> 2;
    const int tr = lane & 3;
    float2 bv[4];
    #pragma unroll
    for (int nf = 0; nf < 4; nf++) {
        int col = bn + wn * 32 + nf * 8 + tr * 2;
        bv[nf].x = bias[col];
        bv[nf].y = bias[col + 1];
    }
    #pragma unroll
    for (int mf = 0; mf < 4; mf++) {
        #pragma unroll
        for (int half = 0; half < 2; half++) {
            int row = bm + wm * 64 + mf * 16 + tq + half * 8;
            float mv = (flags & 2) ? mask[row] : 1.0f;
            float* dst = C + (size_t)row * N + bn + wn * 32 + tr * 2;
            #pragma unroll
            for (int nf = 0; nf < 4; nf++) {
                float2 v;
                v.x = acc[mf][nf][half * 2 + 0] + bv[nf].x;
                v.y = acc[mf][nf][half * 2 + 1] + bv[nf].y;
                if (flags & 1) { v.x = fmaxf(v.x, 0.f); v.y = fmaxf(v.y, 0.f); }
                v.x *= mv; v.y *= mv;
                *(float2*)(dst + nf * 8) = v;
            }
        }
    }
}

// ===========================================================================
// Combined-weight precompute -> bf16 hi/lo planes
// ===========================================================================
__global__ void __launch_bounds__(256)
comb_kernel(const float* __restrict__ Wq, const float* __restrict__ Wqf,
            const float* __restrict__ Wk, const float* __restrict__ Wkf)
{
    const int isk = blockIdx.z;
    const float* Wbig = isk ? Wk : Wq;
    const float* Wf   = isk ? Wkf : Wqf;
    __nv_bfloat16* outh = isk ? g_Wkch : g_Wqch;
    __nv_bfloat16* outl = isk ? g_Wkcl : g_Wqcl;
    const int h  = blockIdx.y;
    const int e0 = blockIdx.x * 128;

    __shared__ float Wfs[FDIM][HDIM + 1];
    __shared__ float Ws[16][128];

    const int tid = threadIdx.x;
    for (int idx = tid; idx < FDIM * HDIM; idx += 256)
        Wfs[idx >> 7][idx & 127] = Wf[idx];

    const int f  = tid & 63;
    const int eg = tid >> 6;
    float acc[32];
    #pragma unroll
    for (int j = 0; j < 32; j++) acc[j] = 0.f;

    for (int d0 = 0; d0 < HDIM; d0 += 16) {
        __syncthreads();
        #pragma unroll
        for (int i = 0; i < 2; i++) {
            int idx = tid + 256 * i;
            int dd  = idx >> 5;
            int c4  = (idx & 31) * 4;
            *(float4*)&Ws[dd][c4] =
                *(const float4*)(Wbig + (size_t)(h * HDIM + d0 + dd) * HID + e0 + c4);
        }
        __syncthreads();
        #pragma unroll
        for (int dd = 0; dd < 16; dd++) {
            float wf = Wfs[f][d0 + dd];
            #pragma unroll
            for (int j = 0; j < 32; j++)
                acc[j] += wf * Ws[dd][eg * 32 + j];
        }
    }
    #pragma unroll
    for (int j = 0; j < 32; j++) {
        size_t idx = (size_t)(h * FDIM + f) * HID + e0 + eg * 32 + j;
        float v = acc[j];
        __nv_bfloat16 hb = __float2bfloat16(v);
        outh[idx] = hb;
        outl[idx] = __float2bfloat16(v - __bfloat162float(hb));
    }
}

__global__ void __launch_bounds__(64)
bias_comb_kernel(const float* __restrict__ bq, const float* __restrict__ Wqf,
                 const float* __restrict__ bk, const float* __restrict__ Wkf)
{
    const int isk = blockIdx.y;
    const float* b  = isk ? bk : bq;
    const float* Wf = isk ? Wkf : Wqf;
    float* out = isk ? g_bkc : g_bqc;
    const int h = blockIdx.x;
    const int f = threadIdx.x;
    float s = 0.f;
    for (int d = 0; d < HDIM; d++) s += Wf[f * HDIM + d] * b[h * HDIM + d];
    out[h * FDIM + f] = s;
}

// ===========================================================================
// kv partial + per-chunk k' column sums (deterministic split-K)
// ===========================================================================
__global__ void __launch_bounds__(256)
kv_partial_kernel()
{
    __shared__ float ks[32][FDIM];
    __shared__ float vs[32][HDIM];

    const int tid = threadIdx.x;
    const int bh  = blockIdx.y;
    const int b   = bh >> 4, h = bh & 15;
    const int s0  = blockIdx.x * (SEQ / KVCH);
    const int fg  = tid >> 4;
    const int eg  = tid & 15;

    float acc[4][8];
    #pragma unroll
    for (int i = 0; i < 4; i++)
        #pragma unroll
        for (int j = 0; j < 8; j++) acc[i][j] = 0.f;
    float ksacc = 0.f;

    for (int ss = 0; ss < SEQ / KVCH; ss += 32) {
        #pragma unroll
        for (int i = 0; i < 2; i++) {
            int idx = tid + 256 * i;
            int sr  = idx >> 4;
            int c4  = (idx & 15) * 4;
            *(float4*)&ks[sr][c4] = *(const float4*)(
                g_kp + ((size_t)(b * SEQ + s0 + ss + sr) * NHEADS + h) * FDIM + c4);
        }
        #pragma unroll
        for (int i = 0; i < 4; i++) {
            int idx = tid + 256 * i;
            int sr  = idx >> 5;
            int c4  = (idx & 31) * 4;
            *(float4*)&vs[sr][c4] = *(const float4*)(
                g_V + (size_t)(b * SEQ + s0 + ss + sr) * HID + h * HDIM + c4);
        }
        __syncthreads();

        #pragma unroll 4
        for (int s = 0; s < 32; s++) {
            float a[4];
            *(float4*)a = *(const float4*)&ks[s][fg * 4];
            float bb[8];
            *(float4*)&bb[0] = *(const float4*)&vs[s][eg * 8];
            *(float4*)&bb[4] = *(const float4*)&vs[s][eg * 8 + 4];
            #pragma unroll
            for (int i = 0; i < 4; i++)
                #pragma unroll
                for (int j = 0; j < 8; j++) acc[i][j] += a[i] * bb[j];
        }
        if (tid < FDIM) {
            #pragma unroll 8
            for (int s = 0; s < 32; s++) ksacc += ks[s][tid];
        }
        __syncthreads();
    }

    float* dst = g_kvpart + ((size_t)blockIdx.x * BHEADS + bh) * FDIM * HDIM;
    #pragma unroll
    for (int i = 0; i < 4; i++)
        #pragma unroll
        for (int j = 0; j < 8; j++)
            dst[(fg * 4 + i) * HDIM + eg * 8 + j] = acc[i][j];
    if (tid < FDIM)
        g_kspart[(blockIdx.x * BHEADS + bh) * FDIM + tid] = ksacc;
}

__global__ void __launch_bounds__(256)
kv_reduce_kernel()
{
    int i = blockIdx.x * 256 + threadIdx.x;
    float s = 0.f;
    #pragma unroll
    for (int c = 0; c < KVCH; c++) s += g_kvpart[(size_t)c * KVELEM + i];
    g_kv[i] = s;
}

__global__ void __launch_bounds__(256)
ksum_reduce_kernel()
{
    int i = blockIdx.x * 256 + threadIdx.x;   // 0..BHEADS*FDIM-1
    float s = 0.f;
    #pragma unroll
    for (int c = 0; c < KVCH; c++) s += g_kspart[c * BHEADS * FDIM + i];
    g_ksum[i] = s;
}

// ===========================================================================
// qkv + normalize -> bf16 hi/lo planes (input to O projection)
// ===========================================================================
__global__ void __launch_bounds__(256)
qkv_kernel()
{
    __shared__ float kvs[FDIM][HDIM];
    __shared__ float qs[32][FDIM];
    __shared__ float kss[FDIM];

    const int tid = threadIdx.x;
    const int h   = blockIdx.y;
    const int bs0 = blockIdx.x * 32;
    const int b   = bs0 / SEQ;
    const int bh  = b * NHEADS + h;

    #pragma unroll
    for (int i = 0; i < 8; i++) {
        int idx = tid + 256 * i;
        int fr  = idx >> 5;
        int c4  = (idx & 31) * 4;
        *(float4*)&kvs[fr][c4] = *(const float4*)(
            g_kv + (size_t)bh * FDIM * HDIM + fr * HDIM + c4);
    }
    if (tid < FDIM) kss[tid] = g_ksum[bh * FDIM + tid];
    #pragma unroll
    for (int i = 0; i < 2; i++) {
        int idx = tid + 256 * i;
        int sr  = idx >> 4;
        int c4  = (idx & 15) * 4;
        *(float4*)&qs[sr][c4] = *(const float4*)(
            g_qp + ((size_t)(bs0 + sr) * NHEADS + h) * FDIM + c4);
    }
    __syncthreads();

    const int sl = tid >> 3;
    const int e0 = (tid & 7) * 16;

    float den = 0.f;
    #pragma unroll 8
    for (int f = 0; f < FDIM; f++) den += qs[sl][f] * kss[f];
    const float inv = 1.0f / (den + 1e-8f);

    float o[16];
    #pragma unroll
    for (int j = 0; j < 16; j++) o[j] = 0.f;
    #pragma unroll 4
    for (int f = 0; f < FDIM; f++) {
        float q = qs[sl][f];
        const float4* kr = (const float4*)&kvs[f][e0];
        #pragma unroll
        for (int j4 = 0; j4 < 4; j4++) {
            float4 kvv = kr[j4];
            o[j4 * 4 + 0] += q * kvv.x;
            o[j4 * 4 + 1] += q * kvv.y;
            o[j4 * 4 + 2] += q * kvv.z;
            o[j4 * 4 + 3] += q * kvv.w;
        }
    }

    uint32_t H[8], L[8];
    #pragma unroll
    for (int p = 0; p < 8; p++)
        split_pack(o[2 * p] * inv, o[2 * p + 1] * inv, H[p], L[p]);
    size_t didx = (size_t)(bs0 + sl) * HID + h * HDIM + e0;
    *(uint4*)&g_ah[didx]     = make_uint4(H[0], H[1], H[2], H[3]);
    *(uint4*)&g_ah[didx + 8] = make_uint4(H[4], H[5], H[6], H[7]);
    *(uint4*)&g_al[didx]     = make_uint4(L[0], L[1], L[2], L[3]);
    *(uint4*)&g_al[didx + 8] = make_uint4(L[4], L[5], L[6], L[7]);
}

// ===========================================================================
extern "C" void kernel_launch(void* const* d_in, const int* in_sizes, int n_in,
                              void* d_out, int out_size)
{
    const float* query = (const float*)d_in[0];
    const float* key_  = (const float*)d_in[1];
    const float* value = (const float*)d_in[2];
    const float* mask  = (const float*)d_in[3];
    const float* Wq    = (const float*)d_in[4];
    const float* bq    = (const float*)d_in[5];
    const float* Wk    = (const float*)d_in[6];
    const float* bk    = (const float*)d_in[7];
    const float* Wv    = (const float*)d_in[8];
    const float* bv    = (const float*)d_in[9];
    const float* Wqf   = (const float*)d_in[10];
    const float* Wkf   = (const float*)d_in[11];
    const float* Wo    = (const float*)d_in[12];
    const float* bo    = (const float*)d_in[13];
    float* out = (float*)d_out;

    cudaFuncSetAttribute(gemm_tc, cudaFuncAttributeMaxDynamicSharedMemorySize, GSMEM);

    const int nbig = (MROWS * HID) / 8;      // 4194304
    const int nw   = (HID * HID) / 8;        // 524288
    conv_kernel<<<(nbig + 255) / 256, 256>>>(query, 0, nbig);
    conv_kernel<<<(nbig + 255) / 256, 256>>>(key_,  1, nbig);
    conv_kernel<<<(nbig + 255) / 256, 256>>>(value, 2, nbig);
    conv_kernel<<<(nw + 255) / 256, 256>>>(Wv, 3, nw);
    conv_kernel<<<(nw + 255) / 256, 256>>>(Wo, 4, nw);

    comb_kernel<<<dim3(HID / 128, NHEADS, 2), 256>>>(Wq, Wqf, Wk, Wkf);
    bias_comb_kernel<<<dim3(NHEADS, 2), 64>>>(bq, Wqf, bk, Wkf);

    // q' = relu(query @ Wqc^T + bqc)      -> g_qp
    gemm_tc<<<dim3(NQP / 128, MROWS / 128), 256, GSMEM>>>(
        0, 0, nullptr, 0, nullptr, 0, mask, 1, NQP);
    // k' = relu(key @ Wkc^T + bkc) * mask -> g_kp
    gemm_tc<<<dim3(NQP / 128, MROWS / 128), 256, GSMEM>>>(
        1, 1, nullptr, 1, nullptr, 1, mask, 3, NQP);
    // V = value @ Wv^T + bv               -> g_V
    gemm_tc<<<dim3(HID / 128, MROWS / 128), 256, GSMEM>>>(
        2, 2, bv, 2, nullptr, 2, mask, 0, HID);

    kv_partial_kernel<<<dim3(KVCH, BHEADS), 256>>>();
    kv_reduce_kernel<<<KVELEM / 256, 256>>>();
    ksum_reduce_kernel<<<(BHEADS * FDIM) / 256, 256>>>();
    qkv_kernel<<<dim3(MROWS / 32, NHEADS), 256>>>();

    // out = attn @ Wo^T + bo
    gemm_tc<<<dim3(HID / 128, MROWS / 128), 256, GSMEM>>>(
        3, 3, bo, 2, out, 3, mask, 0, HID);
}